// round 1
// baseline (speedup 1.0000x reference)
#include <cuda_runtime.h>
#include <cstdint>
#include <math.h>

// Problem constants
#define B_    2
#define L_    2048
#define T_    (B_*L_)        // 4096 tokens
#define D_    1024
#define F_    4096
#define E_    8
#define KTOP  2
#define NPAIR (T_*KTOP)      // 8192 token-expert pairs

// ---------------- scratch (device globals; no allocation) ----------------
__device__ float g_hbuf[(size_t)NPAIR * F_];   // 134 MB: gelu(h) per pair
__device__ float g_ybuf[(size_t)NPAIR * D_];   // 33.5 MB: weighted y per pair
__device__ float g_probs[T_ * E_];
__device__ int   g_topk_e[T_ * KTOP];
__device__ float g_topk_w[T_ * KTOP];
__device__ int   g_expert_list[E_ * T_];       // pair ids per expert
__device__ int   g_expert_count[E_];

// ---------------- helpers ----------------
__device__ __forceinline__ uint32_t f2tf32(float f) {
    uint32_t r;
    asm("cvt.rna.tf32.f32 %0, %1;" : "=r"(r) : "f"(f));
    return r;
}

__device__ __forceinline__ void mma_tf32(float c[4], const uint32_t a[4], const uint32_t b[2]) {
    asm volatile(
        "mma.sync.aligned.m16n8k8.row.col.f32.tf32.tf32.f32 "
        "{%0,%1,%2,%3}, {%4,%5,%6,%7}, {%8,%9}, {%0,%1,%2,%3};"
        : "+f"(c[0]), "+f"(c[1]), "+f"(c[2]), "+f"(c[3])
        : "r"(a[0]), "r"(a[1]), "r"(a[2]), "r"(a[3]), "r"(b[0]), "r"(b[1]));
}

__device__ __forceinline__ float gelu_exact(float v) {
    return 0.5f * v * (1.0f + erff(v * 0.70710678118654752f));
}

// ---------------- kernel 0: zero counters ----------------
__global__ void zero_kernel() {
    if (threadIdx.x < E_) g_expert_count[threadIdx.x] = 0;
}

// ---------------- kernel 1: gating (one warp per token) ----------------
__global__ void gate_kernel(const float* __restrict__ x,
                            const float* __restrict__ Wg,
                            const float* __restrict__ bg) {
    int gwarp = (blockIdx.x * blockDim.x + threadIdx.x) >> 5;
    int lane  = threadIdx.x & 31;
    if (gwarp >= T_) return;
    const float* xr = x + (size_t)gwarp * D_;

    float acc[E_];
#pragma unroll
    for (int e = 0; e < E_; e++) acc[e] = 0.f;

    for (int d = lane; d < D_; d += 32) {
        float xv = xr[d];
        float4 w0 = *(const float4*)(Wg + d * E_);
        float4 w1 = *(const float4*)(Wg + d * E_ + 4);
        acc[0] += xv * w0.x; acc[1] += xv * w0.y;
        acc[2] += xv * w0.z; acc[3] += xv * w0.w;
        acc[4] += xv * w1.x; acc[5] += xv * w1.y;
        acc[6] += xv * w1.z; acc[7] += xv * w1.w;
    }
#pragma unroll
    for (int e = 0; e < E_; e++)
#pragma unroll
        for (int off = 16; off > 0; off >>= 1)
            acc[e] += __shfl_xor_sync(0xFFFFFFFFu, acc[e], off);

    if (lane == 0) {
        float s[E_];
#pragma unroll
        for (int e = 0; e < E_; e++) s[e] = acc[e] + bg[e];

        // top-2 (first-occurrence tie-break, matches lax.top_k)
        int e0 = 0;
#pragma unroll
        for (int e = 1; e < E_; e++) if (s[e] > s[e0]) e0 = e;
        int e1 = -1;
#pragma unroll
        for (int e = 0; e < E_; e++) {
            if (e == e0) continue;
            if (e1 < 0 || s[e] > s[e1]) e1 = e;
        }

        // softmax over top-2
        float z1 = __expf(s[e1] - s[e0]);
        float w0 = 1.0f / (1.0f + z1);
        float w1 = z1 / (1.0f + z1);

        // full softmax probs
        float m = s[e0];
        float zsum = 0.f, p[E_];
#pragma unroll
        for (int e = 0; e < E_; e++) { p[e] = __expf(s[e] - m); zsum += p[e]; }
        float inv = 1.0f / zsum;
#pragma unroll
        for (int e = 0; e < E_; e++) g_probs[gwarp * E_ + e] = p[e] * inv;

        g_topk_e[gwarp * 2 + 0] = e0;
        g_topk_e[gwarp * 2 + 1] = e1;
        g_topk_w[gwarp * 2 + 0] = w0;
        g_topk_w[gwarp * 2 + 1] = w1;
    }
}

// ---------------- kernel 2: routing ----------------
__global__ void route_kernel() {
    int t = blockIdx.x * blockDim.x + threadIdx.x;
    if (t >= T_) return;
#pragma unroll
    for (int k = 0; k < KTOP; k++) {
        int e = g_topk_e[t * 2 + k];
        int pos = atomicAdd(&g_expert_count[e], 1);
        g_expert_list[e * T_ + pos] = t * 2 + k;
    }
}

// ---------------- kernel 3: load-balance loss (deterministic reduce) ----------------
__global__ void loss_kernel(float* __restrict__ out) {
    __shared__ float sh_pp[256][E_];
    __shared__ float sh_pf[256][E_];
    int tid = threadIdx.x;
    float pp[E_], pf[E_];
#pragma unroll
    for (int e = 0; e < E_; e++) { pp[e] = 0.f; pf[e] = 0.f; }
    for (int t = tid; t < T_; t += 256) {
#pragma unroll
        for (int e = 0; e < E_; e++) pp[e] += g_probs[t * E_ + e];
        pf[g_topk_e[2 * t]]     += 1.f;
        pf[g_topk_e[2 * t + 1]] += 1.f;
    }
#pragma unroll
    for (int e = 0; e < E_; e++) { sh_pp[tid][e] = pp[e]; sh_pf[tid][e] = pf[e]; }
    __syncthreads();
    if (tid == 0) {
        float loss = 0.f;
        for (int e = 0; e < E_; e++) {
            float a = 0.f, b = 0.f;
            for (int i = 0; i < 256; i++) { a += sh_pf[i][e]; b += sh_pp[i][e]; }
            loss += (a / (float)T_) * (b / (float)T_);
        }
        out[(size_t)T_ * D_] = loss * (float)E_;
    }
}

// ---------------- kernels 4/5: tiled tf32 GEMM with gather + fused epilogue ----------------
// MODE 1: H = gelu(gather(x) @ W1[e] + b1[e])           -> g_hbuf
// MODE 2: Y = (gather(g_hbuf) @ W2[e] + b2[e]) * w_pair -> g_ybuf
#define BM 128
#define BN 128
#define BK 16
#define MAX_MTILES (T_ / BM)   // 32

template <int MODE>
__global__ void __launch_bounds__(256, 2)
ffn_gemm(const float* __restrict__ X,
         const float* __restrict__ W1, const float* __restrict__ b1,
         const float* __restrict__ W2, const float* __restrict__ b2) {
    const int e     = blockIdx.y >> 5;      // / MAX_MTILES
    const int mtile = blockIdx.y & 31;
    const int cnt   = g_expert_count[e];
    const int m0    = mtile * BM;
    if (m0 >= cnt) return;
    const int nb = blockIdx.x * BN;

    const int KDIM = (MODE == 1) ? D_ : F_;
    const int NDIM = (MODE == 1) ? F_ : D_;
    const float* Bmat = (MODE == 1) ? (W1 + (size_t)e * D_ * F_)
                                    : (W2 + (size_t)e * F_ * D_);
    const float* bias = (MODE == 1) ? (b1 + e * F_) : (b2 + e * D_);

    __shared__ float As[BM][BK + 4];
    __shared__ float Bs[BK][BN + 4];
    __shared__ const float* sRow[BM];
    __shared__ int   sP[BM];
    __shared__ float sW[BM];

    const int tid = threadIdx.x;

    for (int i = tid; i < BM; i += 256) {
        int idx = m0 + i;
        int valid = (idx < cnt);
        int p = valid ? g_expert_list[e * T_ + idx] : 0;
        sP[i] = valid ? p : -1;
        sRow[i] = (MODE == 1) ? (X + (size_t)(p >> 1) * D_)
                              : (g_hbuf + (size_t)p * F_);
        if (MODE == 2) sW[i] = g_topk_w[p];
    }
    __syncthreads();

    const int warp = tid >> 5, lane = tid & 31;
    const int wm = warp >> 2;     // 0..1 -> 64 rows
    const int wn = warp & 3;      // 0..3 -> 32 cols
    const int gid = lane >> 2, tig = lane & 3;

    float acc[4][4][4];
#pragma unroll
    for (int mi = 0; mi < 4; mi++)
#pragma unroll
        for (int ni = 0; ni < 4; ni++)
#pragma unroll
            for (int q = 0; q < 4; q++) acc[mi][ni][q] = 0.f;

    for (int k0 = 0; k0 < KDIM; k0 += BK) {
        // A tile: 128 rows x 16 (gathered rows), 512 float4
#pragma unroll
        for (int i = 0; i < 2; i++) {
            int j = tid + i * 256;
            int r = j >> 2, q = j & 3;
            float4 v = *(const float4*)(sRow[r] + k0 + q * 4);
            *(float4*)&As[r][q * 4] = v;
        }
        // B tile: 16 rows x 128, coalesced
#pragma unroll
        for (int i = 0; i < 2; i++) {
            int j = tid + i * 256;
            int r = j >> 5, q = j & 31;
            float4 v = *(const float4*)(Bmat + (size_t)(k0 + r) * NDIM + nb + q * 4);
            *(float4*)&Bs[r][q * 4] = v;
        }
        __syncthreads();

#pragma unroll
        for (int ks = 0; ks < 2; ks++) {
            uint32_t af[4][4];
            uint32_t bf[4][2];
#pragma unroll
            for (int mi = 0; mi < 4; mi++) {
                int r = wm * 64 + mi * 16 + gid;
                int c = ks * 8 + tig;
                af[mi][0] = f2tf32(As[r][c]);
                af[mi][1] = f2tf32(As[r + 8][c]);
                af[mi][2] = f2tf32(As[r][c + 4]);
                af[mi][3] = f2tf32(As[r + 8][c + 4]);
            }
#pragma unroll
            for (int ni = 0; ni < 4; ni++) {
                int c = wn * 32 + ni * 8 + gid;
                bf[ni][0] = f2tf32(Bs[ks * 8 + tig][c]);
                bf[ni][1] = f2tf32(Bs[ks * 8 + tig + 4][c]);
            }
#pragma unroll
            for (int mi = 0; mi < 4; mi++)
#pragma unroll
                for (int ni = 0; ni < 4; ni++)
                    mma_tf32(acc[mi][ni], af[mi], bf[ni]);
        }
        __syncthreads();
    }

    // epilogue
#pragma unroll
    for (int mi = 0; mi < 4; mi++) {
#pragma unroll
        for (int ni = 0; ni < 4; ni++) {
            int c0 = nb + wn * 32 + ni * 8 + tig * 2;  // even column
            float bi0 = __ldg(&bias[c0]);
            float bi1 = __ldg(&bias[c0 + 1]);
#pragma unroll
            for (int half = 0; half < 2; half++) {
                int r = wm * 64 + mi * 16 + gid + half * 8;
                int p = sP[r];
                if (p >= 0) {
                    float v0 = acc[mi][ni][half * 2 + 0] + bi0;
                    float v1 = acc[mi][ni][half * 2 + 1] + bi1;
                    if (MODE == 1) {
                        v0 = gelu_exact(v0);
                        v1 = gelu_exact(v1);
                        float2* dst = (float2*)(g_hbuf + (size_t)p * F_ + c0);
                        *dst = make_float2(v0, v1);
                    } else {
                        float w = sW[r];
                        float2* dst = (float2*)(g_ybuf + (size_t)p * D_ + c0);
                        *dst = make_float2(v0 * w, v1 * w);
                    }
                }
            }
        }
    }
}

// ---------------- kernel 6: combine (sum 2 slots per token) ----------------
__global__ void combine_kernel(float* __restrict__ out) {
    int i = blockIdx.x * blockDim.x + threadIdx.x;   // over T_*D_/4 float4s
    if (i >= T_ * D_ / 4) return;
    int t = i / (D_ / 4);
    int dq = i % (D_ / 4);
    float4 a = *(const float4*)(g_ybuf + (size_t)(2 * t) * D_ + dq * 4);
    float4 b = *(const float4*)(g_ybuf + (size_t)(2 * t + 1) * D_ + dq * 4);
    float4 r;
    r.x = a.x + b.x; r.y = a.y + b.y; r.z = a.z + b.z; r.w = a.w + b.w;
    *(float4*)(out + (size_t)i * 4) = r;
}

// ---------------- launch ----------------
extern "C" void kernel_launch(void* const* d_in, const int* in_sizes, int n_in,
                              void* d_out, int out_size) {
    const float* x  = (const float*)d_in[0];
    const float* Wg = (const float*)d_in[1];
    const float* bg = (const float*)d_in[2];
    const float* W1 = (const float*)d_in[3];
    const float* b1 = (const float*)d_in[4];
    const float* W2 = (const float*)d_in[5];
    const float* b2 = (const float*)d_in[6];
    float* out = (float*)d_out;

    zero_kernel<<<1, 32>>>();
    gate_kernel<<<T_ / 8, 256>>>(x, Wg, bg);   // 8 warps/block = 8 tokens/block
    route_kernel<<<T_ / 256, 256>>>();
    loss_kernel<<<1, 256>>>(out);

    dim3 g1(F_ / BN, E_ * MAX_MTILES);
    ffn_gemm<1><<<g1, 256>>>(x, W1, b1, W2, b2);
    dim3 g2(D_ / BN, E_ * MAX_MTILES);
    ffn_gemm<2><<<g2, 256>>>(x, W1, b1, W2, b2);

    combine_kernel<<<(T_ * D_ / 4 + 255) / 256, 256>>>(out);
}

// round 3
// speedup vs baseline: 1.6532x; 1.6532x over previous
#include <cuda_runtime.h>
#include <cstdint>
#include <math.h>

// Problem constants
#define B_    2
#define L_    2048
#define T_    (B_*L_)        // 4096 tokens
#define D_    1024
#define F_    4096
#define E_    8
#define KTOP  2
#define NPAIR (T_*KTOP)      // 8192 pairs

// GEMM tile config
#define BM 128
#define BN 128
#define BK 32

// ---------------- scratch (device globals; no allocation) ----------------
__device__ float g_xr[(size_t)T_ * D_];        // tf32-rounded x
__device__ float g_hbuf[(size_t)NPAIR * F_];   // tf32-rounded gelu(h)
__device__ float g_ybuf[(size_t)NPAIR * D_];
__device__ float g_probs[T_ * E_];
__device__ int   g_topk_e[T_ * KTOP];
__device__ float g_topk_w[T_ * KTOP];
__device__ int   g_expert_list[E_ * T_];
__device__ int   g_expert_count[E_];
__device__ float g_part_pf[16 * E_];
__device__ float g_part_pp[16 * E_];

// ---------------- helpers ----------------
__device__ __forceinline__ uint32_t f2tf32(float f) {
    uint32_t r;
    asm("cvt.rna.tf32.f32 %0, %1;" : "=r"(r) : "f"(f));
    return r;
}

__device__ __forceinline__ void mma_tf32(float c[4], const uint32_t a[4], const uint32_t b[2]) {
    asm volatile(
        "mma.sync.aligned.m16n8k8.row.col.f32.tf32.tf32.f32 "
        "{%0,%1,%2,%3}, {%4,%5,%6,%7}, {%8,%9}, {%0,%1,%2,%3};"
        : "+f"(c[0]), "+f"(c[1]), "+f"(c[2]), "+f"(c[3])
        : "r"(a[0]), "r"(a[1]), "r"(a[2]), "r"(a[3]), "r"(b[0]), "r"(b[1]));
}

__device__ __forceinline__ uint32_t smem_u32(const void* p) {
    uint32_t a;
    asm("{ .reg .u64 t; cvta.to.shared.u64 t, %1; cvt.u32.u64 %0, t; }" : "=r"(a) : "l"(p));
    return a;
}

#define CP16(dst, src)  asm volatile("cp.async.cg.shared.global [%0], [%1], 16;" :: "r"(dst), "l"(src))
#define CP_COMMIT()     asm volatile("cp.async.commit_group;" ::: "memory")
#define CP_WAIT(n)      asm volatile("cp.async.wait_group %0;" :: "n"(n) : "memory")

__device__ __forceinline__ float gelu_exact(float v) {
    return 0.5f * v * (1.0f + erff(v * 0.70710678118654752f));
}

// ---------------- small kernels ----------------
__global__ void zero_kernel() {
    if (threadIdx.x < E_) g_expert_count[threadIdx.x] = 0;
}

__global__ void gate_kernel(const float* __restrict__ x,
                            const float* __restrict__ Wg,
                            const float* __restrict__ bg) {
    int gwarp = (blockIdx.x * blockDim.x + threadIdx.x) >> 5;
    int lane  = threadIdx.x & 31;
    if (gwarp >= T_) return;
    const float* xr = x + (size_t)gwarp * D_;

    float acc[E_];
#pragma unroll
    for (int e = 0; e < E_; e++) acc[e] = 0.f;
    for (int d = lane; d < D_; d += 32) {
        float xv = xr[d];
        float4 w0 = *(const float4*)(Wg + d * E_);
        float4 w1 = *(const float4*)(Wg + d * E_ + 4);
        acc[0] += xv * w0.x; acc[1] += xv * w0.y;
        acc[2] += xv * w0.z; acc[3] += xv * w0.w;
        acc[4] += xv * w1.x; acc[5] += xv * w1.y;
        acc[6] += xv * w1.z; acc[7] += xv * w1.w;
    }
#pragma unroll
    for (int e = 0; e < E_; e++)
#pragma unroll
        for (int off = 16; off > 0; off >>= 1)
            acc[e] += __shfl_xor_sync(0xFFFFFFFFu, acc[e], off);

    if (lane == 0) {
        float s[E_];
#pragma unroll
        for (int e = 0; e < E_; e++) s[e] = acc[e] + bg[e];
        int e0 = 0;
#pragma unroll
        for (int e = 1; e < E_; e++) if (s[e] > s[e0]) e0 = e;
        int e1 = -1;
#pragma unroll
        for (int e = 0; e < E_; e++) {
            if (e == e0) continue;
            if (e1 < 0 || s[e] > s[e1]) e1 = e;
        }
        float z1 = __expf(s[e1] - s[e0]);
        float w0 = 1.0f / (1.0f + z1);
        float w1 = z1 / (1.0f + z1);
        float m = s[e0], zsum = 0.f, p[E_];
#pragma unroll
        for (int e = 0; e < E_; e++) { p[e] = __expf(s[e] - m); zsum += p[e]; }
        float inv = 1.0f / zsum;
#pragma unroll
        for (int e = 0; e < E_; e++) g_probs[gwarp * E_ + e] = p[e] * inv;
        g_topk_e[gwarp * 2 + 0] = e0;
        g_topk_e[gwarp * 2 + 1] = e1;
        g_topk_w[gwarp * 2 + 0] = w0;
        g_topk_w[gwarp * 2 + 1] = w1;
    }
}

__global__ void route_kernel() {
    int t = blockIdx.x * blockDim.x + threadIdx.x;
    if (t >= T_) return;
#pragma unroll
    for (int k = 0; k < KTOP; k++) {
        int e = g_topk_e[t * 2 + k];
        int pos = atomicAdd(&g_expert_count[e], 1);
        g_expert_list[e * T_ + pos] = t * 2 + k;
    }
}

__global__ void loss1_kernel() {
    __shared__ float spp[E_][257];
    __shared__ float spf[E_][257];
    int tid = threadIdx.x;
    int t = blockIdx.x * 256 + tid;
    float f[E_];
#pragma unroll
    for (int e = 0; e < E_; e++) f[e] = 0.f;
    f[g_topk_e[2 * t]]     += 1.f;
    f[g_topk_e[2 * t + 1]] += 1.f;
#pragma unroll
    for (int e = 0; e < E_; e++) {
        spp[e][tid] = g_probs[t * E_ + e];
        spf[e][tid] = f[e];
    }
    __syncthreads();
    int wid = tid >> 5, lane = tid & 31;
    if (wid < E_) {
        float a = 0.f, b = 0.f;
#pragma unroll
        for (int j = 0; j < 8; j++) {
            a += spf[wid][lane + j * 32];
            b += spp[wid][lane + j * 32];
        }
#pragma unroll
        for (int off = 16; off > 0; off >>= 1) {
            a += __shfl_xor_sync(0xFFFFFFFFu, a, off);
            b += __shfl_xor_sync(0xFFFFFFFFu, b, off);
        }
        if (lane == 0) {
            g_part_pf[blockIdx.x * E_ + wid] = a;
            g_part_pp[blockIdx.x * E_ + wid] = b;
        }
    }
}

__global__ void loss2_kernel(float* __restrict__ out) {
    __shared__ float sl[E_];
    int e = threadIdx.x;
    if (e < E_) {
        float a = 0.f, b = 0.f;
        for (int i = 0; i < 16; i++) { a += g_part_pf[i * E_ + e]; b += g_part_pp[i * E_ + e]; }
        sl[e] = (a / (float)T_) * (b / (float)T_);
    }
    __syncthreads();
    if (e == 0) {
        float loss = 0.f;
        for (int i = 0; i < E_; i++) loss += sl[i];
        out[(size_t)T_ * D_] = loss * (float)E_;
    }
}

// tf32-round x
__global__ void roundx_kernel(const float* __restrict__ x) {
    int i = blockIdx.x * blockDim.x + threadIdx.x;   // over T_*D_/4
    if (i >= T_ * D_ / 4) return;
    float4 v = *(const float4*)(x + (size_t)i * 4);
    v.x = __uint_as_float(f2tf32(v.x));
    v.y = __uint_as_float(f2tf32(v.y));
    v.z = __uint_as_float(f2tf32(v.z));
    v.w = __uint_as_float(f2tf32(v.w));
    *(float4*)(g_xr + (size_t)i * 4) = v;
}

// ---------------- pipelined tf32 GEMM ----------------
// smem layout (dynamic):
//  [0,512)      sP  (128 int)
//  [512,1024)   sW  (128 float)
//  [1024,1536)  sB  (128 float bias)
//  stage s in {0,1}: A at 1536 + s*35840 (128 rows x 36 floats = 18432 B)
//                    B at A + 18432     (32 rows x 136 floats = 17408 B)
#define APAD 36
#define BPAD 136
#define STG_BYTES (128*APAD*4 + BK*BPAD*4)   // 35840
#define SMEM_GEMM (1536 + 2*STG_BYTES)       // 73216

template <int MODE>
__global__ void __launch_bounds__(256, 2)
ffn_gemm(const float* __restrict__ Wmat_g, const float* __restrict__ bias_g) {
    constexpr int KDIM = (MODE == 1) ? D_ : F_;
    constexpr int NDIM = (MODE == 1) ? F_ : D_;
    constexpr int CHUNKS = KDIM / BK;

    const int e     = blockIdx.y >> 5;
    const int mtile = blockIdx.y & 31;
    const int cnt   = g_expert_count[e];
    const int m0    = mtile * BM;
    if (m0 >= cnt) return;
    const int nb = blockIdx.x * BN;

    extern __shared__ char smem[];
    const uint32_t sbase = smem_u32(smem);
    int*   sP = (int*)smem;
    float* sW = (float*)(smem + 512);
    float* sB = (float*)(smem + 1024);

    const int tid = threadIdx.x;
    const int warp = tid >> 5, lane = tid & 31;

    // token metadata
    {
        int idx = m0 + (tid & 127);
        if (tid < 128) {
            int p = (idx < cnt) ? g_expert_list[e * T_ + idx] : -1;
            sP[tid] = p;
            sW[tid] = (MODE == 2 && p >= 0) ? g_topk_w[p] : 0.f;
        } else {
            sB[tid - 128] = __ldg(bias_g + (size_t)e * NDIM + nb + (tid - 128));
        }
    }
    __syncthreads();

    // per-thread A source pointers: rows r_i = (tid>>3) + i*32, col q = tid&7
    const float* aSrc[4];
    const int q = tid & 7;
#pragma unroll
    for (int i = 0; i < 4; i++) {
        int r = (tid >> 3) + i * 32;
        int p = sP[r];
        if (p < 0) p = g_expert_list[e * T_];   // safe fallback row
        aSrc[i] = (MODE == 1) ? (g_xr + (size_t)(p >> 1) * D_ + q * 4)
                              : (g_hbuf + (size_t)p * F_ + q * 4);
    }
    // B source: row rb = tid>>5 + i*8? -> j = tid + i*256: r=j>>5, q2=j&31
    const float* Wmat = Wmat_g + (size_t)e * KDIM * NDIM;

    const uint32_t aOff[2] = { sbase + 1536u, sbase + 1536u + STG_BYTES };
    const uint32_t bOff[2] = { aOff[0] + 128 * APAD * 4, aOff[1] + 128 * APAD * 4 };

    // load stage macro
    auto load_stage = [&](int c, int s) {
        const int k0 = c * BK;
        // A: 1024 float4 -> 4 per thread
#pragma unroll
        for (int i = 0; i < 4; i++) {
            int r = (tid >> 3) + i * 32;
            uint32_t dst = aOff[s] + (uint32_t)(r * APAD * 4 + q * 16);
            CP16(dst, aSrc[i] + k0);
        }
        // B: 1024 float4 -> 4 per thread
#pragma unroll
        for (int i = 0; i < 4; i++) {
            int j = tid + i * 256;
            int rb = j >> 5, qb = j & 31;
            uint32_t dst = bOff[s] + (uint32_t)(rb * BPAD * 4 + qb * 16);
            CP16(dst, Wmat + (size_t)(k0 + rb) * NDIM + nb + qb * 4);
        }
        CP_COMMIT();
    };

    const int wm = warp >> 2;     // 0..1 -> 64 rows
    const int wn = warp & 3;      // 0..3 -> 32 cols
    const int gid = lane >> 2, tig = lane & 3;

    float acc[4][4][4];
#pragma unroll
    for (int mi = 0; mi < 4; mi++)
#pragma unroll
        for (int ni = 0; ni < 4; ni++)
#pragma unroll
            for (int qq = 0; qq < 4; qq++) acc[mi][ni][qq] = 0.f;

    load_stage(0, 0);

    for (int c = 0; c < CHUNKS; c++) {
        const int s = c & 1;
        if (c + 1 < CHUNKS) {
            load_stage(c + 1, s ^ 1);
            CP_WAIT(1);
        } else {
            CP_WAIT(0);
        }
        __syncthreads();

        const float* As = (const float*)(smem + 1536 + s * STG_BYTES);
        const float* Bs = As + 128 * APAD;

#pragma unroll
        for (int ks = 0; ks < 4; ks++) {
            uint32_t af[4][4];
            uint32_t bf[4][2];
#pragma unroll
            for (int mi = 0; mi < 4; mi++) {
                int r = wm * 64 + mi * 16 + gid;
                int cc = ks * 8 + tig;
                af[mi][0] = __float_as_uint(As[r * APAD + cc]);
                af[mi][1] = __float_as_uint(As[(r + 8) * APAD + cc]);
                af[mi][2] = __float_as_uint(As[r * APAD + cc + 4]);
                af[mi][3] = __float_as_uint(As[(r + 8) * APAD + cc + 4]);
            }
#pragma unroll
            for (int ni = 0; ni < 4; ni++) {
                int cc = wn * 32 + ni * 8 + gid;
                bf[ni][0] = f2tf32(Bs[(ks * 8 + tig) * BPAD + cc]);
                bf[ni][1] = f2tf32(Bs[(ks * 8 + tig + 4) * BPAD + cc]);
            }
#pragma unroll
            for (int mi = 0; mi < 4; mi++)
#pragma unroll
                for (int ni = 0; ni < 4; ni++)
                    mma_tf32(acc[mi][ni], af[mi], bf[ni]);
        }
        __syncthreads();   // protect stage buffer reuse
    }

    // epilogue
#pragma unroll
    for (int mi = 0; mi < 4; mi++) {
#pragma unroll
        for (int ni = 0; ni < 4; ni++) {
            int cl = wn * 32 + ni * 8 + tig * 2;   // local col (even)
            int c0 = nb + cl;
            float bi0 = sB[cl];
            float bi1 = sB[cl + 1];
#pragma unroll
            for (int half = 0; half < 2; half++) {
                int r = wm * 64 + mi * 16 + gid + half * 8;
                int p = sP[r];
                if (p >= 0) {
                    float v0 = acc[mi][ni][half * 2 + 0] + bi0;
                    float v1 = acc[mi][ni][half * 2 + 1] + bi1;
                    if (MODE == 1) {
                        v0 = gelu_exact(v0);
                        v1 = gelu_exact(v1);
                        // store tf32-rounded so GEMM2 A needs no cvt
                        v0 = __uint_as_float(f2tf32(v0));
                        v1 = __uint_as_float(f2tf32(v1));
                        *(float2*)(g_hbuf + (size_t)p * F_ + c0) = make_float2(v0, v1);
                    } else {
                        float w = sW[r];
                        *(float2*)(g_ybuf + (size_t)p * D_ + c0) = make_float2(v0 * w, v1 * w);
                    }
                }
            }
        }
    }
}

// ---------------- combine ----------------
__global__ void combine_kernel(float* __restrict__ out) {
    int i = blockIdx.x * blockDim.x + threadIdx.x;   // over T_*D_/4
    if (i >= T_ * D_ / 4) return;
    int t = i / (D_ / 4);
    int dq = i % (D_ / 4);
    float4 a = *(const float4*)(g_ybuf + (size_t)(2 * t) * D_ + dq * 4);
    float4 b = *(const float4*)(g_ybuf + (size_t)(2 * t + 1) * D_ + dq * 4);
    float4 r;
    r.x = a.x + b.x; r.y = a.y + b.y; r.z = a.z + b.z; r.w = a.w + b.w;
    *(float4*)(out + (size_t)i * 4) = r;
}

// ---------------- launch ----------------
extern "C" void kernel_launch(void* const* d_in, const int* in_sizes, int n_in,
                              void* d_out, int out_size) {
    const float* x  = (const float*)d_in[0];
    const float* Wg = (const float*)d_in[1];
    const float* bg = (const float*)d_in[2];
    const float* W1 = (const float*)d_in[3];
    const float* b1 = (const float*)d_in[4];
    const float* W2 = (const float*)d_in[5];
    const float* b2 = (const float*)d_in[6];
    float* out = (float*)d_out;

    static bool attr_set = false;
    if (!attr_set) {
        cudaFuncSetAttribute(ffn_gemm<1>, cudaFuncAttributeMaxDynamicSharedMemorySize, SMEM_GEMM);
        cudaFuncSetAttribute(ffn_gemm<2>, cudaFuncAttributeMaxDynamicSharedMemorySize, SMEM_GEMM);
        attr_set = true;
    }

    zero_kernel<<<1, 32>>>();
    gate_kernel<<<T_ / 8, 256>>>(x, Wg, bg);
    route_kernel<<<T_ / 256, 256>>>();
    loss1_kernel<<<16, 256>>>();
    loss2_kernel<<<1, 32>>>(out);
    roundx_kernel<<<(T_ * D_ / 4 + 255) / 256, 256>>>(x);

    dim3 g1(F_ / BN, E_ * 32);
    ffn_gemm<1><<<g1, 256, SMEM_GEMM>>>(W1, b1);
    dim3 g2(D_ / BN, E_ * 32);
    ffn_gemm<2><<<g2, 256, SMEM_GEMM>>>(W2, b2);

    combine_kernel<<<(T_ * D_ / 4 + 255) / 256, 256>>>(out);
}

// round 6
// speedup vs baseline: 2.4835x; 1.5022x over previous
#include <cuda_runtime.h>
#include <cuda_fp16.h>
#include <cstdint>
#include <math.h>

// Problem constants
#define B_    2
#define L_    2048
#define T_    (B_*L_)        // 4096 tokens
#define D_    1024
#define F_    4096
#define E_    8
#define KTOP  2
#define NPAIR (T_*KTOP)      // 8192 pairs

// GEMM tile config
#define BM 128
#define BN 128
#define BK 32

// smem pitches (bytes)
#define PA_B 80                       // A row: 32 halves = 64B + 16B pad
#define PB_B 544                      // B kk-row: 128 n-pairs = 512B + 32B pad
#define A_STG (BM * PA_B)             // 10240
#define B_STG ((BK/2) * PB_B)         // 8704
#define STG   (A_STG + B_STG)         // 18944
#define SMEM_GEMM (1536 + 2 * STG)    // 39424

// ---------------- scratch (device globals; no allocation) ----------------
// NOTE: device symbols are ONLY referenced from device code (never passed as
// host-side kernel args — host sees the shadow symbol, not the device copy).
__device__ __half g_xh[(size_t)T_ * D_];
__device__ __half g_w1p[(size_t)E_ * D_ * F_];   // [e][D/2][F][2] k-pair interleaved
__device__ __half g_w2p[(size_t)E_ * F_ * D_];   // [e][F/2][D][2]
__device__ __half g_hh[(size_t)NPAIR * F_];
__device__ float  g_ybuf[(size_t)NPAIR * D_];
__device__ float  g_probs[T_ * E_];
__device__ int    g_topk_e[T_ * KTOP];
__device__ float  g_topk_w[T_ * KTOP];
__device__ int    g_expert_list[E_ * T_];
__device__ int    g_expert_count[E_];
__device__ float  g_part_pf[16 * E_];
__device__ float  g_part_pp[16 * E_];

// ---------------- helpers ----------------
__device__ __forceinline__ uint32_t smem_u32(const void* p) {
    uint32_t a;
    asm("{ .reg .u64 t; cvta.to.shared.u64 t, %1; cvt.u32.u64 %0, t; }" : "=r"(a) : "l"(p));
    return a;
}

#define CP16(dst, src)  asm volatile("cp.async.cg.shared.global [%0], [%1], 16;" :: "r"(dst), "l"(src))
#define CP_COMMIT()     asm volatile("cp.async.commit_group;" ::: "memory")
#define CP_WAIT(n)      asm volatile("cp.async.wait_group %0;" :: "n"(n) : "memory")

__device__ __forceinline__ void mma_f16(float c[4], const uint32_t a[4],
                                        uint32_t b0, uint32_t b1) {
    asm volatile(
        "mma.sync.aligned.m16n8k16.row.col.f32.f16.f16.f32 "
        "{%0,%1,%2,%3}, {%4,%5,%6,%7}, {%8,%9}, {%0,%1,%2,%3};"
        : "+f"(c[0]), "+f"(c[1]), "+f"(c[2]), "+f"(c[3])
        : "r"(a[0]), "r"(a[1]), "r"(a[2]), "r"(a[3]), "r"(b0), "r"(b1));
}

__device__ __forceinline__ float gelu_exact(float v) {
    return 0.5f * v * (1.0f + erff(v * 0.70710678118654752f));
}

// ---------------- small kernels ----------------
__global__ void zero_kernel() {
    if (threadIdx.x < E_) g_expert_count[threadIdx.x] = 0;
}

__global__ void gate_kernel(const float* __restrict__ x,
                            const float* __restrict__ Wg,
                            const float* __restrict__ bg) {
    int gwarp = (blockIdx.x * blockDim.x + threadIdx.x) >> 5;
    int lane  = threadIdx.x & 31;
    if (gwarp >= T_) return;
    const float* xr = x + (size_t)gwarp * D_;

    float acc[E_];
#pragma unroll
    for (int e = 0; e < E_; e++) acc[e] = 0.f;
    for (int d = lane; d < D_; d += 32) {
        float xv = xr[d];
        float4 w0 = *(const float4*)(Wg + d * E_);
        float4 w1 = *(const float4*)(Wg + d * E_ + 4);
        acc[0] += xv * w0.x; acc[1] += xv * w0.y;
        acc[2] += xv * w0.z; acc[3] += xv * w0.w;
        acc[4] += xv * w1.x; acc[5] += xv * w1.y;
        acc[6] += xv * w1.z; acc[7] += xv * w1.w;
    }
#pragma unroll
    for (int e = 0; e < E_; e++)
#pragma unroll
        for (int off = 16; off > 0; off >>= 1)
            acc[e] += __shfl_xor_sync(0xFFFFFFFFu, acc[e], off);

    if (lane == 0) {
        float s[E_];
#pragma unroll
        for (int e = 0; e < E_; e++) s[e] = acc[e] + bg[e];
        int e0 = 0;
#pragma unroll
        for (int e = 1; e < E_; e++) if (s[e] > s[e0]) e0 = e;
        int e1 = -1;
#pragma unroll
        for (int e = 0; e < E_; e++) {
            if (e == e0) continue;
            if (e1 < 0 || s[e] > s[e1]) e1 = e;
        }
        float z1 = __expf(s[e1] - s[e0]);
        float w0 = 1.0f / (1.0f + z1);
        float w1 = z1 / (1.0f + z1);
        float m = s[e0], zsum = 0.f, p[E_];
#pragma unroll
        for (int e = 0; e < E_; e++) { p[e] = __expf(s[e] - m); zsum += p[e]; }
        float inv = 1.0f / zsum;
#pragma unroll
        for (int e = 0; e < E_; e++) g_probs[gwarp * E_ + e] = p[e] * inv;
        g_topk_e[gwarp * 2 + 0] = e0;
        g_topk_e[gwarp * 2 + 1] = e1;
        g_topk_w[gwarp * 2 + 0] = w0;
        g_topk_w[gwarp * 2 + 1] = w1;
    }
}

__global__ void route_kernel() {
    int t = blockIdx.x * blockDim.x + threadIdx.x;
    if (t >= T_) return;
#pragma unroll
    for (int k = 0; k < KTOP; k++) {
        int e = g_topk_e[t * 2 + k];
        int pos = atomicAdd(&g_expert_count[e], 1);
        g_expert_list[e * T_ + pos] = t * 2 + k;
    }
}

__global__ void loss1_kernel() {
    __shared__ float spp[E_][257];
    __shared__ float spf[E_][257];
    int tid = threadIdx.x;
    int t = blockIdx.x * 256 + tid;
    float f[E_];
#pragma unroll
    for (int e = 0; e < E_; e++) f[e] = 0.f;
    f[g_topk_e[2 * t]]     += 1.f;
    f[g_topk_e[2 * t + 1]] += 1.f;
#pragma unroll
    for (int e = 0; e < E_; e++) {
        spp[e][tid] = g_probs[t * E_ + e];
        spf[e][tid] = f[e];
    }
    __syncthreads();
    int wid = tid >> 5, lane = tid & 31;
    if (wid < E_) {
        float a = 0.f, b = 0.f;
#pragma unroll
        for (int j = 0; j < 8; j++) {
            a += spf[wid][lane + j * 32];
            b += spp[wid][lane + j * 32];
        }
#pragma unroll
        for (int off = 16; off > 0; off >>= 1) {
            a += __shfl_xor_sync(0xFFFFFFFFu, a, off);
            b += __shfl_xor_sync(0xFFFFFFFFu, b, off);
        }
        if (lane == 0) {
            g_part_pf[blockIdx.x * E_ + wid] = a;
            g_part_pp[blockIdx.x * E_ + wid] = b;
        }
    }
}

__global__ void loss2_kernel(float* __restrict__ out) {
    __shared__ float sl[E_];
    int e = threadIdx.x;
    if (e < E_) {
        float a = 0.f, b = 0.f;
        for (int i = 0; i < 16; i++) { a += g_part_pf[i * E_ + e]; b += g_part_pp[i * E_ + e]; }
        sl[e] = (a / (float)T_) * (b / (float)T_);
    }
    __syncthreads();
    if (e == 0) {
        float loss = 0.f;
        for (int i = 0; i < E_; i++) loss += sl[i];
        out[(size_t)T_ * D_] = loss * (float)E_;
    }
}

// x fp32 -> g_xh fp16 (device symbol referenced in device code only)
__global__ void cvt_x_kernel(const float* __restrict__ src) {
    int i = blockIdx.x * blockDim.x + threadIdx.x;
    if (i >= T_ * D_ / 4) return;
    float4 v = *(const float4*)(src + (size_t)i * 4);
    ((__half2*)g_xh)[2 * (size_t)i]     = __floats2half2_rn(v.x, v.y);
    ((__half2*)g_xh)[2 * (size_t)i + 1] = __floats2half2_rn(v.z, v.w);
}

// W[e][K][N] fp32 -> g_w{1,2}p[e][K/2][N][2] fp16 (k-pair interleave)
template <int WHICH>
__global__ void wperm_kernel(const float* __restrict__ W) {
    constexpr int K = (WHICH == 1) ? D_ : F_;
    constexpr int N = (WHICH == 1) ? F_ : D_;
    __half* wp = (WHICH == 1) ? g_w1p : g_w2p;
    int i = blockIdx.x * blockDim.x + threadIdx.x;
    constexpr int perE = (K / 2) * (N / 2);
    if (i >= E_ * perE) return;
    int e   = i / perE;
    int rem = i % perE;
    int kk  = rem / (N / 2);
    int n   = (rem % (N / 2)) * 2;
    const float* src = W + ((size_t)e * K + 2 * kk) * N + n;
    float2 r0 = *(const float2*)(src);
    float2 r1 = *(const float2*)(src + N);
    __half2 h0 = __floats2half2_rn(r0.x, r1.x);  // {k even, k odd} for col n
    __half2 h1 = __floats2half2_rn(r0.y, r1.y);  // for col n+1
    __half2* dst = (__half2*)(wp + ((size_t)e * (K / 2) + kk) * N * 2 + n * 2);
    dst[0] = h0;
    dst[1] = h1;
}

// ---------------- pipelined fp16 GEMM (manual fragments) ----------------
// smem: [0,512) sP, [512,1024) sW, [1024,1536) sB, stages at 1536 + s*STG
template <int MODE>
__global__ void __launch_bounds__(256, 2)
ffn_gemm(const float* __restrict__ bias_g) {
    constexpr int KDIM = (MODE == 1) ? D_ : F_;
    constexpr int NDIM = (MODE == 1) ? F_ : D_;
    constexpr int CHUNKS = KDIM / BK;

    const int e     = blockIdx.y >> 5;
    const int mtile = blockIdx.y & 31;
    const int cnt   = g_expert_count[e];
    const int m0    = mtile * BM;
    if (m0 >= cnt) return;
    const int nb = blockIdx.x * BN;

    extern __shared__ char smem[];
    const uint32_t sbase = smem_u32(smem);
    int*   sP = (int*)smem;
    float* sW = (float*)(smem + 512);
    float* sB = (float*)(smem + 1024);

    const int tid = threadIdx.x;
    const int warp = tid >> 5, lane = tid & 31;

    {
        if (tid < 128) {
            int idx = m0 + tid;
            int p = (idx < cnt) ? g_expert_list[e * T_ + idx] : -1;
            sP[tid] = p;
            sW[tid] = (MODE == 2 && p >= 0) ? g_topk_w[p] : 0.f;
        } else {
            sB[tid - 128] = __ldg(bias_g + (size_t)e * NDIM + nb + (tid - 128));
        }
    }
    __syncthreads();

    // A gmem sources: rows r = tid>>2, tid>>2+64; 16B chunk qa = tid&3
    const int qa = tid & 3;
    const __half* aSrc[2];
#pragma unroll
    for (int i = 0; i < 2; i++) {
        int r = (tid >> 2) + i * 64;
        int p = sP[r];
        if (p < 0) p = g_expert_list[e * T_];
        aSrc[i] = ((MODE == 1) ? (g_xh + (size_t)(p >> 1) * D_)
                               : (g_hh + (size_t)p * F_)) + qa * 8;
    }
    // B gmem (permuted, via device symbol): kk-rows of NDIM*2 halves
    const __half* Wp = ((MODE == 1) ? g_w1p : g_w2p)
                       + (size_t)e * (KDIM / 2) * (NDIM * 2) + (size_t)nb * 2;
    const int qb = tid & 31;   // 32 x 16B = 512B per kk-row

    const uint32_t stg0 = sbase + 1536u;
    const uint32_t stg1 = stg0 + STG;

    auto load_stage = [&](int c, int s) {
        const uint32_t base = s ? stg1 : stg0;
        const int k0  = c * BK;       // halves (A)
        const int kk0 = c * (BK / 2); // B kk-row
#pragma unroll
        for (int i = 0; i < 2; i++) {
            int r = (tid >> 2) + i * 64;
            CP16(base + (uint32_t)(r * PA_B + qa * 16), aSrc[i] + k0);
        }
#pragma unroll
        for (int i = 0; i < 2; i++) {
            int rb = (tid >> 5) + i * 8;
            CP16(base + A_STG + (uint32_t)(rb * PB_B + qb * 16),
                 Wp + (size_t)(kk0 + rb) * (NDIM * 2) + qb * 8);
        }
        CP_COMMIT();
    };

    const int wm = warp >> 2;     // 0..1 -> 64 rows
    const int wn = warp & 3;      // 0..3 -> 32 cols
    const int gid = lane >> 2, tig = lane & 3;

    float acc[4][4][4];
#pragma unroll
    for (int mi = 0; mi < 4; mi++)
#pragma unroll
        for (int ni = 0; ni < 4; ni++)
#pragma unroll
            for (int qq = 0; qq < 4; qq++) acc[mi][ni][qq] = 0.f;

    load_stage(0, 0);

    for (int c = 0; c < CHUNKS; c++) {
        const int s = c & 1;
        if (c + 1 < CHUNKS) {
            load_stage(c + 1, s ^ 1);
            CP_WAIT(1);
        } else {
            CP_WAIT(0);
        }
        __syncthreads();

        const char* stg = smem + 1536 + s * STG;
        const char* As = stg;
        const char* Bs = stg + A_STG;

#pragma unroll
        for (int ks = 0; ks < 2; ks++) {
            // A frags: a0=(g, k2t) a1=(g+8, k2t) a2=(g, k2t+8) a3=(g+8, k2t+8)
            uint32_t a[4][4];
#pragma unroll
            for (int mi = 0; mi < 4; mi++) {
                int row = wm * 64 + mi * 16 + gid;
                int kb  = (ks * 16 + 2 * tig) * 2;   // byte offset in row
                a[mi][0] = *(const uint32_t*)(As + row * PA_B + kb);
                a[mi][1] = *(const uint32_t*)(As + (row + 8) * PA_B + kb);
                a[mi][2] = *(const uint32_t*)(As + row * PA_B + kb + 16);
                a[mi][3] = *(const uint32_t*)(As + (row + 8) * PA_B + kb + 16);
            }
            // B frags: b0 = {B[k2t][n],B[k2t+1][n]}, b1 = same at k+8
            uint32_t b[4][2];
#pragma unroll
            for (int ni = 0; ni < 4; ni++) {
                int n = wn * 32 + ni * 8 + gid;
                b[ni][0] = *(const uint32_t*)(Bs + (ks * 8 + tig) * PB_B + n * 4);
                b[ni][1] = *(const uint32_t*)(Bs + (ks * 8 + 4 + tig) * PB_B + n * 4);
            }
#pragma unroll
            for (int mi = 0; mi < 4; mi++)
#pragma unroll
                for (int ni = 0; ni < 4; ni++)
                    mma_f16(acc[mi][ni], a[mi], b[ni][0], b[ni][1]);
        }
        __syncthreads();
    }

    // epilogue
#pragma unroll
    for (int mi = 0; mi < 4; mi++) {
#pragma unroll
        for (int ni = 0; ni < 4; ni++) {
            int cl = wn * 32 + ni * 8 + tig * 2;
            int c0 = nb + cl;
            float bi0 = sB[cl];
            float bi1 = sB[cl + 1];
#pragma unroll
            for (int half = 0; half < 2; half++) {
                int r = wm * 64 + mi * 16 + gid + half * 8;
                int p = sP[r];
                if (p >= 0) {
                    float v0 = acc[mi][ni][half * 2 + 0] + bi0;
                    float v1 = acc[mi][ni][half * 2 + 1] + bi1;
                    if (MODE == 1) {
                        v0 = gelu_exact(v0);
                        v1 = gelu_exact(v1);
                        *(__half2*)(g_hh + (size_t)p * F_ + c0) = __floats2half2_rn(v0, v1);
                    } else {
                        float w = sW[r];
                        *(float2*)(g_ybuf + (size_t)p * D_ + c0) = make_float2(v0 * w, v1 * w);
                    }
                }
            }
        }
    }
}

// ---------------- combine ----------------
__global__ void combine_kernel(float* __restrict__ out) {
    int i = blockIdx.x * blockDim.x + threadIdx.x;
    if (i >= T_ * D_ / 4) return;
    int t = i / (D_ / 4);
    int dq = i % (D_ / 4);
    float4 a = *(const float4*)(g_ybuf + (size_t)(2 * t) * D_ + dq * 4);
    float4 b = *(const float4*)(g_ybuf + (size_t)(2 * t + 1) * D_ + dq * 4);
    float4 r;
    r.x = a.x + b.x; r.y = a.y + b.y; r.z = a.z + b.z; r.w = a.w + b.w;
    *(float4*)(out + (size_t)i * 4) = r;
}

// ---------------- launch ----------------
extern "C" void kernel_launch(void* const* d_in, const int* in_sizes, int n_in,
                              void* d_out, int out_size) {
    const float* x  = (const float*)d_in[0];
    const float* Wg = (const float*)d_in[1];
    const float* bg = (const float*)d_in[2];
    const float* W1 = (const float*)d_in[3];
    const float* b1 = (const float*)d_in[4];
    const float* W2 = (const float*)d_in[5];
    const float* b2 = (const float*)d_in[6];
    float* out = (float*)d_out;

    zero_kernel<<<1, 32>>>();
    gate_kernel<<<T_ / 8, 256>>>(x, Wg, bg);
    route_kernel<<<T_ / 256, 256>>>();
    loss1_kernel<<<16, 256>>>();
    loss2_kernel<<<1, 32>>>(out);

    cvt_x_kernel<<<(T_ * D_ / 4 + 255) / 256, 256>>>(x);
    {
        int n1 = E_ * (D_ / 2) * (F_ / 2);
        wperm_kernel<1><<<(n1 + 255) / 256, 256>>>(W1);
        int n2 = E_ * (F_ / 2) * (D_ / 2);
        wperm_kernel<2><<<(n2 + 255) / 256, 256>>>(W2);
    }

    dim3 g1(F_ / BN, E_ * 32);
    ffn_gemm<1><<<g1, 256, SMEM_GEMM>>>(b1);
    dim3 g2(D_ / BN, E_ * 32);
    ffn_gemm<2><<<g2, 256, SMEM_GEMM>>>(b2);

    combine_kernel<<<(T_ * D_ / 4 + 255) / 256, 256>>>(out);
}

// round 8
// speedup vs baseline: 2.5179x; 1.0139x over previous
#include <cuda_runtime.h>
#include <cuda_fp16.h>
#include <cstdint>
#include <math.h>

// Problem constants
#define B_    2
#define L_    2048
#define T_    (B_*L_)        // 4096 tokens
#define D_    1024
#define F_    4096
#define E_    8
#define KTOP  2
#define NPAIR (T_*KTOP)      // 8192 pairs

// GEMM tile config
#define BM 128
#define BN 128
#define BK 32

// smem pitches (bytes)
#define PA_B 80                       // A row: 32 halves = 64B + 16B pad
#define PB_B 272                      // B row: 128 halves = 256B + 16B pad
#define A_STG (BM * PA_B)             // 10240
#define B_STG (BK * PB_B)             // 8704
#define STG   (A_STG + B_STG)         // 18944
#define SMEM_GEMM (1536 + 2 * STG)    // 39424  (< 48KB: no attribute needed)

// ---------------- scratch (device globals; device-code access ONLY) ----------------
__device__ __half g_xh[(size_t)T_ * D_];
__device__ __half g_w1h[(size_t)E_ * D_ * F_];   // row-major [e][k=D][n=F]
__device__ __half g_w2h[(size_t)E_ * F_ * D_];   // row-major [e][k=F][n=D]
__device__ __half g_hh[(size_t)NPAIR * F_];
__device__ float  g_ybuf[(size_t)NPAIR * D_];
__device__ float  g_probs[T_ * E_];
__device__ int    g_topk_e[T_ * KTOP];
__device__ float  g_topk_w[T_ * KTOP];
__device__ int    g_expert_list[E_ * T_];
__device__ int    g_expert_count[E_];
__device__ float  g_part_pf[16 * E_];
__device__ float  g_part_pp[16 * E_];

// ---------------- helpers ----------------
__device__ __forceinline__ uint32_t smem_u32(const void* p) {
    uint32_t a;
    asm("{ .reg .u64 t; cvta.to.shared.u64 t, %1; cvt.u32.u64 %0, t; }" : "=r"(a) : "l"(p));
    return a;
}

#define CP16(dst, src)  asm volatile("cp.async.cg.shared.global [%0], [%1], 16;" :: "r"(dst), "l"(src))
#define CP_COMMIT()     asm volatile("cp.async.commit_group;" ::: "memory")
#define CP_WAIT(n)      asm volatile("cp.async.wait_group %0;" :: "n"(n) : "memory")

#define LDSM_X4(r, a) \
    asm volatile("ldmatrix.sync.aligned.m8n8.x4.shared.b16 {%0,%1,%2,%3}, [%4];" \
        : "=r"((r)[0]), "=r"((r)[1]), "=r"((r)[2]), "=r"((r)[3]) : "r"(a))

#define LDSM_X4T(r, a) \
    asm volatile("ldmatrix.sync.aligned.m8n8.x4.trans.shared.b16 {%0,%1,%2,%3}, [%4];" \
        : "=r"((r)[0]), "=r"((r)[1]), "=r"((r)[2]), "=r"((r)[3]) : "r"(a))

__device__ __forceinline__ void mma_f16(float c[4], const uint32_t a[4],
                                        uint32_t b0, uint32_t b1) {
    asm volatile(
        "mma.sync.aligned.m16n8k16.row.col.f32.f16.f16.f32 "
        "{%0,%1,%2,%3}, {%4,%5,%6,%7}, {%8,%9}, {%0,%1,%2,%3};"
        : "+f"(c[0]), "+f"(c[1]), "+f"(c[2]), "+f"(c[3])
        : "r"(a[0]), "r"(a[1]), "r"(a[2]), "r"(a[3]), "r"(b0), "r"(b1));
}

__device__ __forceinline__ float gelu_exact(float v) {
    return 0.5f * v * (1.0f + erff(v * 0.70710678118654752f));
}

// ---------------- small kernels ----------------
__global__ void zero_kernel() {
    if (threadIdx.x < E_) g_expert_count[threadIdx.x] = 0;
}

__global__ void gate_kernel(const float* __restrict__ x,
                            const float* __restrict__ Wg,
                            const float* __restrict__ bg) {
    int gwarp = (blockIdx.x * blockDim.x + threadIdx.x) >> 5;
    int lane  = threadIdx.x & 31;
    if (gwarp >= T_) return;
    const float* xr = x + (size_t)gwarp * D_;

    float acc[E_];
#pragma unroll
    for (int e = 0; e < E_; e++) acc[e] = 0.f;
    for (int d = lane; d < D_; d += 32) {
        float xv = xr[d];
        float4 w0 = *(const float4*)(Wg + d * E_);
        float4 w1 = *(const float4*)(Wg + d * E_ + 4);
        acc[0] += xv * w0.x; acc[1] += xv * w0.y;
        acc[2] += xv * w0.z; acc[3] += xv * w0.w;
        acc[4] += xv * w1.x; acc[5] += xv * w1.y;
        acc[6] += xv * w1.z; acc[7] += xv * w1.w;
    }
#pragma unroll
    for (int e = 0; e < E_; e++)
#pragma unroll
        for (int off = 16; off > 0; off >>= 1)
            acc[e] += __shfl_xor_sync(0xFFFFFFFFu, acc[e], off);

    if (lane == 0) {
        float s[E_];
#pragma unroll
        for (int e = 0; e < E_; e++) s[e] = acc[e] + bg[e];
        int e0 = 0;
#pragma unroll
        for (int e = 1; e < E_; e++) if (s[e] > s[e0]) e0 = e;
        int e1 = -1;
#pragma unroll
        for (int e = 0; e < E_; e++) {
            if (e == e0) continue;
            if (e1 < 0 || s[e] > s[e1]) e1 = e;
        }
        float z1 = __expf(s[e1] - s[e0]);
        float w0 = 1.0f / (1.0f + z1);
        float w1 = z1 / (1.0f + z1);
        float m = s[e0], zsum = 0.f, p[E_];
#pragma unroll
        for (int e = 0; e < E_; e++) { p[e] = __expf(s[e] - m); zsum += p[e]; }
        float inv = 1.0f / zsum;
#pragma unroll
        for (int e = 0; e < E_; e++) g_probs[gwarp * E_ + e] = p[e] * inv;
        g_topk_e[gwarp * 2 + 0] = e0;
        g_topk_e[gwarp * 2 + 1] = e1;
        g_topk_w[gwarp * 2 + 0] = w0;
        g_topk_w[gwarp * 2 + 1] = w1;
    }
}

__global__ void route_kernel() {
    int t = blockIdx.x * blockDim.x + threadIdx.x;
    if (t >= T_) return;
#pragma unroll
    for (int k = 0; k < KTOP; k++) {
        int e = g_topk_e[t * 2 + k];
        int pos = atomicAdd(&g_expert_count[e], 1);
        g_expert_list[e * T_ + pos] = t * 2 + k;
    }
}

__global__ void loss1_kernel() {
    __shared__ float spp[E_][257];
    __shared__ float spf[E_][257];
    int tid = threadIdx.x;
    int t = blockIdx.x * 256 + tid;
    float f[E_];
#pragma unroll
    for (int e = 0; e < E_; e++) f[e] = 0.f;
    f[g_topk_e[2 * t]]     += 1.f;
    f[g_topk_e[2 * t + 1]] += 1.f;
#pragma unroll
    for (int e = 0; e < E_; e++) {
        spp[e][tid] = g_probs[t * E_ + e];
        spf[e][tid] = f[e];
    }
    __syncthreads();
    int wid = tid >> 5, lane = tid & 31;
    if (wid < E_) {
        float a = 0.f, b = 0.f;
#pragma unroll
        for (int j = 0; j < 8; j++) {
            a += spf[wid][lane + j * 32];
            b += spp[wid][lane + j * 32];
        }
#pragma unroll
        for (int off = 16; off > 0; off >>= 1) {
            a += __shfl_xor_sync(0xFFFFFFFFu, a, off);
            b += __shfl_xor_sync(0xFFFFFFFFu, b, off);
        }
        if (lane == 0) {
            g_part_pf[blockIdx.x * E_ + wid] = a;
            g_part_pp[blockIdx.x * E_ + wid] = b;
        }
    }
}

__global__ void loss2_kernel(float* __restrict__ out) {
    __shared__ float sl[E_];
    int e = threadIdx.x;
    if (e < E_) {
        float a = 0.f, b = 0.f;
        for (int i = 0; i < 16; i++) { a += g_part_pf[i * E_ + e]; b += g_part_pp[i * E_ + e]; }
        sl[e] = (a / (float)T_) * (b / (float)T_);
    }
    __syncthreads();
    if (e == 0) {
        float loss = 0.f;
        for (int i = 0; i < E_; i++) loss += sl[i];
        out[(size_t)T_ * D_] = loss * (float)E_;
    }
}

// x fp32 -> g_xh fp16
__global__ void cvt_x_kernel(const float* __restrict__ src) {
    int i = blockIdx.x * blockDim.x + threadIdx.x;
    if (i >= T_ * D_ / 4) return;
    float4 v = *(const float4*)(src + (size_t)i * 4);
    ((__half2*)g_xh)[2 * (size_t)i]     = __floats2half2_rn(v.x, v.y);
    ((__half2*)g_xh)[2 * (size_t)i + 1] = __floats2half2_rn(v.z, v.w);
}

// W fp32 -> g_w{1,2}h fp16
template <int WHICH>
__global__ void cvt_w_kernel(const float* __restrict__ src) {
    __half* dst = (WHICH == 1) ? g_w1h : g_w2h;
    const int n4 = E_ * D_ * F_ / 4;
    int i = blockIdx.x * blockDim.x + threadIdx.x;
    if (i >= n4) return;
    float4 v = *(const float4*)(src + (size_t)i * 4);
    ((__half2*)dst)[2 * (size_t)i]     = __floats2half2_rn(v.x, v.y);
    ((__half2*)dst)[2 * (size_t)i + 1] = __floats2half2_rn(v.z, v.w);
}

// ---------------- 2-stage pipelined fp16 GEMM with ldmatrix ----------------
// smem: [0,512) sP, [512,1024) sW, [1024,1536) sB, stages at 1536 + s*STG
template <int MODE>
__global__ void __launch_bounds__(256, 2)
ffn_gemm(const float* __restrict__ bias_g) {
    constexpr int KDIM = (MODE == 1) ? D_ : F_;
    constexpr int NDIM = (MODE == 1) ? F_ : D_;
    constexpr int CHUNKS = KDIM / BK;

    const int e     = blockIdx.y >> 5;
    const int mtile = blockIdx.y & 31;
    const int cnt   = g_expert_count[e];
    const int m0    = mtile * BM;
    if (m0 >= cnt) return;
    const int nb = blockIdx.x * BN;

    extern __shared__ char smem[];
    const uint32_t sbase = smem_u32(smem);
    int*   sP = (int*)smem;
    float* sW = (float*)(smem + 512);
    float* sB = (float*)(smem + 1024);

    const int tid = threadIdx.x;
    const int warp = tid >> 5, lane = tid & 31;

    {
        if (tid < 128) {
            int idx = m0 + tid;
            int p = (idx < cnt) ? g_expert_list[e * T_ + idx] : -1;
            sP[tid] = p;
            sW[tid] = (MODE == 2 && p >= 0) ? g_topk_w[p] : 0.f;
        } else {
            sB[tid - 128] = __ldg(bias_g + (size_t)e * NDIM + nb + (tid - 128));
        }
    }
    __syncthreads();

    // A gmem sources: rows r = tid>>2, tid>>2+64; 16B chunk qa = tid&3
    const int qa = tid & 3;
    const __half* aSrc[2];
#pragma unroll
    for (int i = 0; i < 2; i++) {
        int r = (tid >> 2) + i * 64;
        int p = sP[r];
        if (p < 0) p = g_expert_list[e * T_];
        aSrc[i] = ((MODE == 1) ? (g_xh + (size_t)(p >> 1) * D_)
                               : (g_hh + (size_t)p * F_)) + qa * 8;
    }
    // B gmem: row-major weights via device symbol
    const __half* Wmat = ((MODE == 1) ? g_w1h : g_w2h) + (size_t)e * KDIM * NDIM;
    const int qb = tid & 15;   // 16 x 16B = 256B per k-row

    const uint32_t stg0 = sbase + 1536u;
    const uint32_t stg1 = stg0 + STG;

    auto load_stage = [&](int c, int s) {
        const uint32_t base = s ? stg1 : stg0;
        const int k0 = c * BK;
        // A: 128 rows x 64B
#pragma unroll
        for (int i = 0; i < 2; i++) {
            int r = (tid >> 2) + i * 64;
            CP16(base + (uint32_t)(r * PA_B + qa * 16), aSrc[i] + k0);
        }
        // B: 32 rows x 256B
#pragma unroll
        for (int i = 0; i < 2; i++) {
            int rb = (tid >> 4) + i * 16;
            CP16(base + A_STG + (uint32_t)(rb * PB_B + qb * 16),
                 Wmat + (size_t)(k0 + rb) * NDIM + nb + qb * 8);
        }
        CP_COMMIT();
    };

    const int wm = warp >> 2;     // 0..1 -> 64 rows
    const int wn = warp & 3;      // 0..3 -> 32 cols
    const int gid = lane >> 2, tig = lane & 3;

    // ldmatrix per-thread base offsets (within stage)
    const uint32_t offA0 = (uint32_t)((wm * 64 + (lane & 15)) * PA_B + (lane >> 4) * 16);
    const uint32_t offB0 = (uint32_t)(A_STG + (((lane >> 3) & 1) * 8 + (lane & 7)) * PB_B
                                      + (wn * 32 + (lane >> 4) * 8) * 2);

    float acc[4][4][4];
#pragma unroll
    for (int mi = 0; mi < 4; mi++)
#pragma unroll
        for (int ni = 0; ni < 4; ni++)
#pragma unroll
            for (int qq = 0; qq < 4; qq++) acc[mi][ni][qq] = 0.f;

    load_stage(0, 0);

    for (int c = 0; c < CHUNKS; c++) {
        const int s = c & 1;
        if (c + 1 < CHUNKS) {
            load_stage(c + 1, s ^ 1);
            CP_WAIT(1);
        } else {
            CP_WAIT(0);
        }
        __syncthreads();

        const uint32_t base = s ? stg1 : stg0;
#pragma unroll
        for (int ks = 0; ks < 2; ks++) {
            uint32_t a[4][4];
            uint32_t b[2][4];
#pragma unroll
            for (int mi = 0; mi < 4; mi++)
                LDSM_X4(a[mi], base + offA0 + (uint32_t)(mi * 16 * PA_B + ks * 32));
#pragma unroll
            for (int np = 0; np < 2; np++)
                LDSM_X4T(b[np], base + offB0 + (uint32_t)(ks * 16 * PB_B + np * 32));
#pragma unroll
            for (int mi = 0; mi < 4; mi++)
#pragma unroll
                for (int ni = 0; ni < 4; ni++)
                    mma_f16(acc[mi][ni], a[mi],
                            b[ni >> 1][(ni & 1) * 2], b[ni >> 1][(ni & 1) * 2 + 1]);
        }
        __syncthreads();
    }

    // epilogue
#pragma unroll
    for (int mi = 0; mi < 4; mi++) {
#pragma unroll
        for (int ni = 0; ni < 4; ni++) {
            int cl = wn * 32 + ni * 8 + tig * 2;
            int c0 = nb + cl;
            float bi0 = sB[cl];
            float bi1 = sB[cl + 1];
#pragma unroll
            for (int half = 0; half < 2; half++) {
                int r = wm * 64 + mi * 16 + gid + half * 8;
                int p = sP[r];
                if (p >= 0) {
                    float v0 = acc[mi][ni][half * 2 + 0] + bi0;
                    float v1 = acc[mi][ni][half * 2 + 1] + bi1;
                    if (MODE == 1) {
                        v0 = gelu_exact(v0);
                        v1 = gelu_exact(v1);
                        *(__half2*)(g_hh + (size_t)p * F_ + c0) = __floats2half2_rn(v0, v1);
                    } else {
                        float w = sW[r];
                        *(float2*)(g_ybuf + (size_t)p * D_ + c0) = make_float2(v0 * w, v1 * w);
                    }
                }
            }
        }
    }
}

// ---------------- combine ----------------
__global__ void combine_kernel(float* __restrict__ out) {
    int i = blockIdx.x * blockDim.x + threadIdx.x;
    if (i >= T_ * D_ / 4) return;
    int t = i / (D_ / 4);
    int dq = i % (D_ / 4);
    float4 a = *(const float4*)(g_ybuf + (size_t)(2 * t) * D_ + dq * 4);
    float4 b = *(const float4*)(g_ybuf + (size_t)(2 * t + 1) * D_ + dq * 4);
    float4 r;
    r.x = a.x + b.x; r.y = a.y + b.y; r.z = a.z + b.z; r.w = a.w + b.w;
    *(float4*)(out + (size_t)i * 4) = r;
}

// ---------------- launch ----------------
extern "C" void kernel_launch(void* const* d_in, const int* in_sizes, int n_in,
                              void* d_out, int out_size) {
    const float* x  = (const float*)d_in[0];
    const float* Wg = (const float*)d_in[1];
    const float* bg = (const float*)d_in[2];
    const float* W1 = (const float*)d_in[3];
    const float* b1 = (const float*)d_in[4];
    const float* W2 = (const float*)d_in[5];
    const float* b2 = (const float*)d_in[6];
    float* out = (float*)d_out;

    zero_kernel<<<1, 32>>>();
    gate_kernel<<<T_ / 8, 256>>>(x, Wg, bg);
    route_kernel<<<T_ / 256, 256>>>();
    loss1_kernel<<<16, 256>>>();
    loss2_kernel<<<1, 32>>>(out);

    cvt_x_kernel<<<(T_ * D_ / 4 + 255) / 256, 256>>>(x);
    cvt_w_kernel<1><<<(E_ * D_ * F_ / 4 + 255) / 256, 256>>>(W1);
    cvt_w_kernel<2><<<(E_ * F_ * D_ / 4 + 255) / 256, 256>>>(W2);

    dim3 g1(F_ / BN, E_ * 32);
    ffn_gemm<1><<<g1, 256, SMEM_GEMM>>>(b1);
    dim3 g2(D_ / BN, E_ * 32);
    ffn_gemm<2><<<g2, 256, SMEM_GEMM>>>(b2);

    combine_kernel<<<(T_ * D_ / 4 + 255) / 256, 256>>>(out);
}